// round 8
// baseline (speedup 1.0000x reference)
#include <cuda_runtime.h>

#define BB 256
#define SS 2048
#define VOCAB 10
#define EE 32
#define HH 64
#define OUTD 10
#define HSTRIDE 68   // 272B rows: 16B-aligned for LDS.128
#define CSC 2.885390081777927f   // 2*log2(e)

typedef unsigned long long ull;

struct Smem {
    float t1f[VOCAB][HH];            // input-proj tables, pre-scaled by CSC
    float t2f[VOCAB][HH];
    unsigned char idx[2][SS];        // nibble-packed tokens
    ull   wd2k[HH / 2][OUTD];        // packed Wd: [k2][o] = (Wd[2k2][o],Wd[2k2+1][o])
    float bdv[OUTD];
    __align__(16) float hist[2][128][HSTRIDE];  // double-window h ring per row
};

// ---- packed f32x2 helpers (sm_103a) ----
__device__ __forceinline__ ull pk2(float lo, float hi) {
    ull r; asm("mov.b64 %0, {%1, %2};" : "=l"(r) : "f"(lo), "f"(hi)); return r;
}
__device__ __forceinline__ void fma2(ull& acc, ull a, ull b) {
    asm("fma.rn.f32x2 %0, %1, %2, %0;" : "+l"(acc) : "l"(a), "l"(b));
}
__device__ __forceinline__ ull add2(ull a, ull b) {
    ull r; asm("add.rn.f32x2 %0, %1, %2;" : "=l"(r) : "l"(a), "l"(b)); return r;
}
__device__ __forceinline__ float2 unpk2(ull x) {
    float lo, hi; asm("mov.b64 {%0, %1}, %2;" : "=f"(lo), "=f"(hi) : "l"(x));
    return make_float2(lo, hi);
}
__device__ __forceinline__ void rowbar(int id) {
    asm volatile("bar.sync %0, 64;" :: "r"(id) : "memory");
}

__global__ __launch_bounds__(128, 1) void rnn_spread_kernel(
    const int* __restrict__ num1, const int* __restrict__ num2,
    const float* __restrict__ embed, const float* __restrict__ Wx,
    const float* __restrict__ Wh, const float* __restrict__ b,
    const float* __restrict__ Wd, const float* __restrict__ bd,
    float* __restrict__ out)
{
    extern __shared__ __align__(16) char smraw[];
    Smem* sm = (Smem*)smraw;

    const int tid  = threadIdx.x;     // 0..127
    const int rowL = tid >> 6;        // warps 0,1 -> row A ; warps 2,3 -> row B
    const int c    = tid & 63;        // hidden column owned by this thread
    const int r0   = blockIdx.x * 2;

    // ---- Prologue ----
    if (tid < HH) {   // input-projection tables (10+10 distinct halves), *CSC
        const int jj = tid;
        float wxa[EE], wxb[EE];
        #pragma unroll
        for (int e = 0; e < EE; e++) {
            wxa[e] = Wx[e * HH + jj];
            wxb[e] = Wx[(EE + e) * HH + jj];
        }
        float bj = b[jj];
        #pragma unroll
        for (int v = 0; v < VOCAB; v++) {
            float a1 = bj, a2 = 0.0f;
            #pragma unroll
            for (int e = 0; e < EE; e++) {
                float ev = embed[v * EE + e];
                a1 = fmaf(ev, wxa[e], a1);
                a2 = fmaf(ev, wxb[e], a2);
            }
            sm->t1f[v][jj] = a1 * CSC;
            sm->t2f[v][jj] = a2 * CSC;
        }
    }
    // packed Wd [k2][o] + bias (true scale)
    for (int i = tid; i < (HH / 2) * OUTD; i += 128) {
        int k2 = i / OUTD, o = i % OUTD;
        sm->wd2k[k2][o] = pk2(Wd[(2 * k2) * OUTD + o], Wd[(2 * k2 + 1) * OUTD + o]);
    }
    if (tid < OUTD) sm->bdv[tid] = bd[tid];
    // token indices, nibble-packed, both rows
    {
        const int* n1A = num1 + (size_t)r0 * SS;
        const int* n2A = num2 + (size_t)r0 * SS;
        for (int i = tid; i < SS; i += 128) {
            sm->idx[0][i] = (unsigned char)(n1A[i] | (n2A[i] << 4));
            sm->idx[1][i] = (unsigned char)(n1A[SS + i] | (n2A[SS + i] << 4));
        }
    }
    // Wh column c as 32 packed k-pairs, pre-scaled by CSC
    ull w[HH / 2];
    #pragma unroll
    for (int m = 0; m < HH / 2; m++)
        w[m] = pk2(CSC * Wh[(2 * m) * HH + c], CSC * Wh[(2 * m + 1) * HH + c]);

    sm->hist[rowL][127][c] = 0.0f;   // h_{-1}=0 (step s reads slot (s+127)&127)
    __syncthreads();

    float* outrow = out + (size_t)(r0 + rowL) * SS * OUTD;

    // software-pipelined input projection for step 0
    int   pkb = sm->idx[rowL][0];
    float t12 = sm->t1f[pkb & 15][c] + sm->t2f[pkb >> 4][c];

    ull oacc[OUTD];     // spread epilogue accumulators (prev window, step c)
    #pragma unroll
    for (int o = 0; o < OUTD; o++) oacc[o] = 0ull;

    for (int s = 0; s < SS; s++) {
        const int sf = s & 63;

        // ---- spread epilogue slice: one k2 every other step, prev window ----
        // (independent of this step's h -> issues into bar-wait / LDS gaps)
        if (s >= 64) {
            if ((sf & 1) == 0) {
                const int k2 = sf >> 1;
                const int pbase = ((((s >> 6) & 1) ^ 1) << 6);
                ull hvv = *((const ull*)sm->hist[rowL][pbase + c] + k2);
                #pragma unroll
                for (int o = 0; o < OUTD; o++)
                    fma2(oacc[o], hvv, sm->wd2k[k2][o]);
            } else if (sf == 63) {
                // write outputs for prev-window step (w-1)*64 + c
                const int gs = s - 127 + c;   // (s>>6 - 1)*64 + c
                float2* op2 = (float2*)(outrow + (size_t)gs * OUTD);
                #pragma unroll
                for (int o = 0; o < OUTD / 2; o++) {
                    float2 ua = unpk2(oacc[2 * o]);
                    float2 ub = unpk2(oacc[2 * o + 1]);
                    op2[o] = make_float2(ua.x + ua.y + sm->bdv[2 * o],
                                         ub.x + ub.y + sm->bdv[2 * o + 1]);
                }
                #pragma unroll
                for (int o = 0; o < OUTD; o++) oacc[o] = 0ull;
            }
        }

        // ---- recurrence step ----
        ull a0 = pk2(t12, 0.0f);   // seed with input projection (off-chain)
        ull a1 = 0ull, a2 = 0ull, a3 = 0ull;
        const ulonglong2* hv =
            (const ulonglong2*)sm->hist[rowL][(s + 127) & 127];
        #pragma unroll
        for (int m = 0; m < 8; m++) {   // 16B broadcast loads; 32 FMA2 total
            ulonglong2 h0 = hv[2 * m];
            fma2(a0, h0.x, w[4 * m + 0]);
            fma2(a1, h0.y, w[4 * m + 1]);
            ulonglong2 h1 = hv[2 * m + 1];
            fma2(a2, h1.x, w[4 * m + 2]);
            fma2(a3, h1.y, w[4 * m + 3]);
        }
        {   // prefetch next step's input projection while FMA chain drains
            int p2 = sm->idx[rowL][(s + 1) & (SS - 1)];
            t12 = sm->t1f[p2 & 15][c] + sm->t2f[p2 >> 4][c];
        }
        float2 u = unpk2(add2(add2(a0, a1), add2(a2, a3)));
        float y = u.x + u.y;            // = 2*log2(e) * z
        float e2; asm("ex2.approx.f32 %0, %1;" : "=f"(e2) : "f"(y));
        float rc; asm("rcp.approx.f32 %0, %1;" : "=f"(rc) : "f"(e2 + 1.0f));
        float hn = fmaf(-2.0f, rc, 1.0f);   // tanh(z)
        sm->hist[rowL][s & 127][c] = hn;
        rowbar(1 + rowL);               // h_s visible to this row's 2 warps
    }

    // ---- final window (w=31, slots 64..127): full epilogue lump ----
    {
        const ull* hp = (const ull*)sm->hist[rowL][64 + c];
        #pragma unroll
        for (int o = 0; o < OUTD; o++) oacc[o] = 0ull;
        #pragma unroll
        for (int k2 = 0; k2 < HH / 2; k2++) {
            ull hvv = hp[k2];
            #pragma unroll
            for (int o = 0; o < OUTD; o++)
                fma2(oacc[o], hvv, sm->wd2k[k2][o]);
        }
        float2* op2 = (float2*)(outrow + (size_t)(31 * 64 + c) * OUTD);
        #pragma unroll
        for (int o = 0; o < OUTD / 2; o++) {
            float2 ua = unpk2(oacc[2 * o]);
            float2 ub = unpk2(oacc[2 * o + 1]);
            op2[o] = make_float2(ua.x + ua.y + sm->bdv[2 * o],
                                 ub.x + ub.y + sm->bdv[2 * o + 1]);
        }
    }
}

extern "C" void kernel_launch(void* const* d_in, const int* in_sizes, int n_in,
                              void* d_out, int out_size)
{
    (void)in_sizes; (void)n_in; (void)out_size;
    const int*   num1  = (const int*)d_in[0];
    const int*   num2  = (const int*)d_in[1];
    const float* embed = (const float*)d_in[2];
    const float* Wx    = (const float*)d_in[3];
    const float* Wh    = (const float*)d_in[4];
    const float* b     = (const float*)d_in[5];
    const float* Wd    = (const float*)d_in[6];
    const float* bd    = (const float*)d_in[7];
    float* out = (float*)d_out;

    cudaFuncSetAttribute(rnn_spread_kernel,
                         cudaFuncAttributeMaxDynamicSharedMemorySize,
                         (int)sizeof(Smem));
    rnn_spread_kernel<<<BB / 2, 128, sizeof(Smem)>>>(
        num1, num2, embed, Wx, Wh, b, Wd, bd, out);
}

// round 9
// speedup vs baseline: 1.0881x; 1.0881x over previous
#include <cuda_runtime.h>

#define BB 256
#define SS 2048
#define VOCAB 10
#define EE 32
#define HH 64
#define OUTD 10
#define HSTRIDE 68   // 272B rows: 16B-aligned
#define CSC 2.885390081777927f   // 2*log2(e)

typedef unsigned long long ull;

// ---- packed f32x2 helpers (sm_103a) ----
__device__ __forceinline__ ull pk2(float lo, float hi) {
    ull r; asm("mov.b64 %0, {%1, %2};" : "=l"(r) : "f"(lo), "f"(hi)); return r;
}
__device__ __forceinline__ void fma2(ull& acc, ull a, ull b) {
    asm("fma.rn.f32x2 %0, %1, %2, %0;" : "+l"(acc) : "l"(a), "l"(b));
}
__device__ __forceinline__ ull add2(ull a, ull b) {
    ull r; asm("add.rn.f32x2 %0, %1, %2;" : "=l"(r) : "l"(a), "l"(b)); return r;
}
__device__ __forceinline__ float2 unpk2(ull x) {
    float lo, hi; asm("mov.b64 {%0, %1}, %2;" : "=f"(lo), "=f"(hi) : "l"(x));
    return make_float2(lo, hi);
}
__device__ __forceinline__ void rowbar(int id) {
    asm volatile("bar.sync %0, 64;" :: "r"(id) : "memory");
}

__global__ __launch_bounds__(128, 1) void rnn_group3_kernel(
    const int* __restrict__ num1, const int* __restrict__ num2,
    const float* __restrict__ embed, const float* __restrict__ Wx,
    const float* __restrict__ Wh, const float* __restrict__ b,
    const float* __restrict__ Wd, const float* __restrict__ bd,
    float* __restrict__ out)
{
    __shared__ float t1f[VOCAB][HH];                       // tables * CSC
    __shared__ float t2f[VOCAB][HH];
    __shared__ unsigned char idx[2][SS];                   // nibble-packed tokens
    __shared__ __align__(16) float hist[2][64][HSTRIDE];   // rotating h history
    __shared__ __align__(8)  float wdkT[OUTD][HH];         // Wd transposed [o][k]
    __shared__ float bd_sh[OUTD];

    const int tid  = threadIdx.x;     // 0..127
    const int rowL = tid >> 6;        // warps 0,1 -> row A ; warps 2,3 -> row B
    const int c    = tid & 63;        // hidden column owned by this thread
    const int barid = 1 + rowL;       // named barrier per row-group
    const int r0   = blockIdx.x * 2;

    // ---- Prologue ----
    if (tid < HH) {   // input-projection tables (10+10 distinct halves), *CSC
        const int jj = tid;
        float wxa[EE], wxb[EE];
        #pragma unroll
        for (int e = 0; e < EE; e++) {
            wxa[e] = Wx[e * HH + jj];
            wxb[e] = Wx[(EE + e) * HH + jj];
        }
        float bj = b[jj];
        #pragma unroll
        for (int v = 0; v < VOCAB; v++) {
            float a1 = bj, a2 = 0.0f;
            #pragma unroll
            for (int e = 0; e < EE; e++) {
                float ev = embed[v * EE + e];
                a1 = fmaf(ev, wxa[e], a1);
                a2 = fmaf(ev, wxb[e], a2);
            }
            t1f[v][jj] = a1 * CSC;
            t2f[v][jj] = a2 * CSC;
        }
    }
    // Wd transposed + bias (true scale)
    for (int i = tid; i < HH * OUTD; i += 128) wdkT[i % OUTD][i / OUTD] = Wd[i];
    if (tid < OUTD) bd_sh[tid] = bd[tid];
    // token indices, nibble-packed, both rows
    {
        const int* n1A = num1 + (size_t)r0 * SS;
        const int* n2A = num2 + (size_t)r0 * SS;
        for (int i = tid; i < SS; i += 128) {
            idx[0][i] = (unsigned char)(n1A[i] | (n2A[i] << 4));
            idx[1][i] = (unsigned char)(n1A[SS + i] | (n2A[SS + i] << 4));
        }
    }
    // Wh column c as 32 packed k-pairs, pre-scaled by CSC
    ull w[HH / 2];
    #pragma unroll
    for (int m = 0; m < HH / 2; m++)
        w[m] = pk2(CSC * Wh[(2 * m) * HH + c], CSC * Wh[(2 * m + 1) * HH + c]);

    hist[rowL][63][c] = 0.0f;   // h_{-1} = 0 (step s reads slot (s+63)&63)
    __syncthreads();

    float* outrow = out + (size_t)(r0 + rowL) * SS * OUTD;

    for (int s = 0; s < SS; s++) {
        const int pkb = idx[rowL][s];
        // seed accumulator with input projection (independent of h -> off-chain)
        ull a0 = pk2(t1f[pkb & 15][c] + t2f[pkb >> 4][c], 0.0f);
        ull a1 = 0ull;

        const ulonglong2* hv = (const ulonglong2*)hist[rowL][(s + 63) & 63];
        #pragma unroll
        for (int m = 0; m < 8; m++) {   // 16B broadcast loads; 32 FMA2 total
            ulonglong2 hh0 = hv[2 * m];
            fma2(a0, hh0.x, w[4 * m + 0]);
            fma2(a1, hh0.y, w[4 * m + 1]);
            ulonglong2 hh1 = hv[2 * m + 1];
            fma2(a0, hh1.x, w[4 * m + 2]);
            fma2(a1, hh1.y, w[4 * m + 3]);
        }
        float2 u = unpk2(add2(a0, a1));
        float y = u.x + u.y;             // = 2*log2(e) * z
        float e2; asm("ex2.approx.f32 %0, %1;" : "=f"(e2) : "f"(y));
        float rc; asm("rcp.approx.f32 %0, %1;" : "=f"(rc) : "f"(e2 + 1.0f));
        float hn = fmaf(-2.0f, rc, 1.0f);   // tanh(z)
        hist[rowL][s & 63][c] = hn;       // conflict-free: bank = c%32
        rowbar(barid);                    // h_s visible to the row-group

        if ((s & 63) == 63) {
            // ---- Fused output projection: thread c handles local step c ----
            const ull* hp = (const ull*)hist[rowL][c];
            ull oacc[OUTD];
            #pragma unroll
            for (int o = 0; o < OUTD; o++) oacc[o] = 0ull;
            #pragma unroll
            for (int k2 = 0; k2 < HH / 2; k2++) {
                ull hvv = hp[k2];
                #pragma unroll
                for (int o = 0; o < OUTD; o++)
                    fma2(oacc[o], hvv, *((const ull*)wdkT[o] + k2));
            }
            float* op = outrow + (size_t)(s - 63 + c) * OUTD;
            float2* op2 = (float2*)op;    // 40B rows -> 8B aligned
            #pragma unroll
            for (int o = 0; o < OUTD / 2; o++) {
                float2 ua = unpk2(oacc[2 * o]);
                float2 ub = unpk2(oacc[2 * o + 1]);
                op2[o] = make_float2(ua.x + ua.y + bd_sh[2 * o],
                                     ub.x + ub.y + bd_sh[2 * o + 1]);
            }
            rowbar(barid);   // epilogue reads done before slots are overwritten
        }
    }
}

extern "C" void kernel_launch(void* const* d_in, const int* in_sizes, int n_in,
                              void* d_out, int out_size)
{
    (void)in_sizes; (void)n_in; (void)out_size;
    const int*   num1  = (const int*)d_in[0];
    const int*   num2  = (const int*)d_in[1];
    const float* embed = (const float*)d_in[2];
    const float* Wx    = (const float*)d_in[3];
    const float* Wh    = (const float*)d_in[4];
    const float* b     = (const float*)d_in[5];
    const float* Wd    = (const float*)d_in[6];
    const float* bd    = (const float*)d_in[7];
    float* out = (float*)d_out;

    rnn_group3_kernel<<<BB / 2, 128>>>(num1, num2, embed, Wx, Wh, b, Wd, bd, out);
}